// round 1
// baseline (speedup 1.0000x reference)
#include <cuda_runtime.h>
#include <math_constants.h>

#define BATCH 4
#define NPIX 4096   // 64*64

// ---------------- scratch (device globals; no cudaMalloc allowed) ----------------
__device__ float g_pool[BATCH * 128 * NPIX];          // maxpool output
__device__ float g_buf1[BATCH * 256 * NPIX];          // conv1 out / h1
__device__ float g_buf2[BATCH * 256 * NPIX];          // conv2 out / h
__device__ float g_br  [4 * BATCH * 64 * NPIX];       // 4 ASPP branch outputs
__device__ float g_q   [4 * BATCH * 64 * NPIX];
__device__ float g_k   [4 * BATCH * 64 * NPIX];
__device__ float g_v   [4 * BATCH * 64 * NPIX];
__device__ float g_pos [64 * NPIX];
__device__ float g_mean[256];
__device__ float g_istd[256];

// ---------------- maxpool 2x2 on [4,128,128,128] -> [4,128,64,64] ----------------
__global__ void maxpool_kernel(const float* __restrict__ x, float* __restrict__ out) {
    int idx = blockIdx.x * blockDim.x + threadIdx.x;
    if (idx >= BATCH * 128 * NPIX) return;
    int p  = idx & (NPIX - 1);
    int bc = idx >> 12;                 // b*128 + c
    int y = p >> 6, xx = p & 63;
    const float* src = x + ((long)bc * 128 + 2 * y) * 128 + 2 * xx;
    out[idx] = fmaxf(fmaxf(src[0], src[1]), fmaxf(src[128], src[129]));
}

// ---------------- generic 3x3 dilated conv, pad=dil, no bias ----------------
// grid: (64 rows, Cout/64, batch).  block: 128 threads.
// per-thread tile: 8 oc x 4 px.  smem: input rows + 68-padded weight tile.
__global__ void __launch_bounds__(128) conv3x3_kernel(
    const float* __restrict__ in, const float* __restrict__ w,
    float* __restrict__ out, int Cin, int Cout, int dil)
{
    const int y   = blockIdx.x;
    const int ocg = blockIdx.y;
    const int b   = blockIdx.z;
    in  += (long)b * Cin  * NPIX;
    out += (long)b * Cout * NPIX;

    const int t   = threadIdx.x;
    const int tpx = t & 15;       // pixel group (4 px each)
    const int tlo = t >> 4;       // oc lane (8 oc each)
    const int px0 = tpx * 4;

    __shared__ float sIn[8 * 3 * 64];   // [ic][ky][x]
    __shared__ float sW [72 * 68];      // [ic*9+tap][oc], 68-padded

    float acc[8][4];
#pragma unroll
    for (int o = 0; o < 8; o++)
#pragma unroll
        for (int p = 0; p < 4; p++) acc[o][p] = 0.f;

    for (int ic0 = 0; ic0 < Cin; ic0 += 8) {
        __syncthreads();
        // input tile: 8 ic x 3 rows x 64 cols
        for (int idx = t; idx < 1536; idx += 128) {
            int ic  = idx / 192;
            int rem = idx - ic * 192;
            int ky  = rem >> 6, xx = rem & 63;
            int ry  = y + (ky - 1) * dil;
            float v = 0.f;
            if (ry >= 0 && ry < 64) v = in[(ic0 + ic) * NPIX + ry * 64 + xx];
            sIn[idx] = v;
        }
        // weight tile: 64 oc x (8 ic * 9 taps)
        for (int idx = t; idx < 4608; idx += 128) {
            int oc = idx / 72;
            int kk = idx - oc * 72;   // ic*9 + tap
            sW[kk * 68 + oc] = w[((long)(ocg * 64 + oc) * Cin + ic0) * 9 + kk];
        }
        __syncthreads();

#pragma unroll
        for (int ic = 0; ic < 8; ic++) {
#pragma unroll
            for (int ky = 0; ky < 3; ky++) {
                const float* rowp = sIn + (ic * 3 + ky) * 64;
#pragma unroll
                for (int kx = 0; kx < 3; kx++) {
                    int xb = px0 + (kx - 1) * dil;
                    float iv[4];
                    iv[0] = (xb + 0 >= 0 && xb + 0 < 64) ? rowp[xb + 0] : 0.f;
                    iv[1] = (xb + 1 >= 0 && xb + 1 < 64) ? rowp[xb + 1] : 0.f;
                    iv[2] = (xb + 2 >= 0 && xb + 2 < 64) ? rowp[xb + 2] : 0.f;
                    iv[3] = (xb + 3 >= 0 && xb + 3 < 64) ? rowp[xb + 3] : 0.f;
                    const float* wp = sW + (ic * 9 + ky * 3 + kx) * 68 + tlo * 8;
                    float4 w0 = *(const float4*)wp;
                    float4 w1 = *(const float4*)(wp + 4);
                    float wv[8] = {w0.x, w0.y, w0.z, w0.w, w1.x, w1.y, w1.z, w1.w};
#pragma unroll
                    for (int o = 0; o < 8; o++)
#pragma unroll
                        for (int p = 0; p < 4; p++) acc[o][p] += wv[o] * iv[p];
                }
            }
        }
    }
#pragma unroll
    for (int o = 0; o < 8; o++) {
        int c = ocg * 64 + tlo * 8 + o;
        float* op = out + (long)c * NPIX + y * 64 + px0;
        op[0] = acc[o][0]; op[1] = acc[o][1]; op[2] = acc[o][2]; op[3] = acc[o][3];
    }
}

// ---------------- 1x1 conv (Cout=64), optional bias ----------------
// grid: (64 px tiles, 1, nimg). block: 256. per-thread 4oc x 4px.
__global__ void __launch_bounds__(256) conv1x1_kernel(
    const float* __restrict__ in, const float* __restrict__ w,
    const float* __restrict__ bias, float* __restrict__ out,
    int Cin, long inStride, long outStride)
{
    const int p0  = blockIdx.x * 64;
    const long img = blockIdx.z;
    in  += img * inStride;
    out += img * outStride;
    const int t = threadIdx.x, tx = t & 15, ty = t >> 4;

    __shared__ float sW [16 * 68];
    __shared__ float sIn[16 * 64];

    float acc[4][4];
#pragma unroll
    for (int r = 0; r < 4; r++)
#pragma unroll
        for (int c = 0; c < 4; c++) acc[r][c] = 0.f;

    for (int ic0 = 0; ic0 < Cin; ic0 += 16) {
        __syncthreads();
        for (int idx = t; idx < 1024; idx += 256) {
            int ic = idx & 15, oc = idx >> 4;
            sW[ic * 68 + oc] = w[(long)oc * Cin + ic0 + ic];
        }
        for (int idx = t; idx < 1024; idx += 256) {
            int ic = idx >> 6, px = idx & 63;
            sIn[idx] = in[(ic0 + ic) * NPIX + p0 + px];
        }
        __syncthreads();
#pragma unroll
        for (int ic = 0; ic < 16; ic++) {
            float4 a  = *(const float4*)(sW  + ic * 68 + ty * 4);
            float4 xv = *(const float4*)(sIn + ic * 64 + tx * 4);
            float av[4] = {a.x, a.y, a.z, a.w};
            float xa[4] = {xv.x, xv.y, xv.z, xv.w};
#pragma unroll
            for (int r = 0; r < 4; r++)
#pragma unroll
                for (int c = 0; c < 4; c++) acc[r][c] += av[r] * xa[c];
        }
    }
#pragma unroll
    for (int r = 0; r < 4; r++) {
        float bb = bias ? bias[ty * 4 + r] : 0.f;
        float* op = out + (long)(ty * 4 + r) * NPIX + p0 + tx * 4;
        op[0] = acc[r][0] + bb; op[1] = acc[r][1] + bb;
        op[2] = acc[r][2] + bb; op[3] = acc[r][3] + bb;
    }
}

// ---------------- BN batch statistics: one block per channel ----------------
__global__ void bnstats_kernel(const float* __restrict__ buf, int C) {
    const int c = blockIdx.x;
    float s = 0.f, ss = 0.f;
    for (int img = 0; img < BATCH; img++) {
        const float* p = buf + ((long)img * C + c) * NPIX;
        for (int i = threadIdx.x; i < NPIX; i += 256) {
            float v = p[i];
            s += v; ss += v * v;
        }
    }
    __shared__ float rs[8], rss[8];
#pragma unroll
    for (int off = 16; off; off >>= 1) {
        s  += __shfl_down_sync(0xffffffffu, s,  off);
        ss += __shfl_down_sync(0xffffffffu, ss, off);
    }
    int lane = threadIdx.x & 31, wp = threadIdx.x >> 5;
    if (!lane) { rs[wp] = s; rss[wp] = ss; }
    __syncthreads();
    if (threadIdx.x == 0) {
        s = 0.f; ss = 0.f;
        for (int i = 0; i < 8; i++) { s += rs[i]; ss += rss[i]; }
        const float M = (float)(BATCH * NPIX);
        float mu  = s / M;
        float var = ss / M - mu * mu;
        g_mean[c] = mu;
        g_istd[c] = rsqrtf(var + 1e-5f);
    }
}

// ---------------- BN apply + ReLU, in-place ----------------
__global__ void bnapply_kernel(float* __restrict__ buf, const float* __restrict__ g,
                               const float* __restrict__ be, int Cmask, int total) {
    for (int idx = blockIdx.x * blockDim.x + threadIdx.x; idx < total;
         idx += gridDim.x * blockDim.x) {
        int c = (idx >> 12) & Cmask;
        float v = buf[idx];
        float y = (v - g_mean[c]) * g_istd[c] * g[c] + be[c];
        buf[idx] = fmaxf(y, 0.f);
    }
}

// ---------------- pos[d][a*64+b] = rel_h[d][b] + rel_w[d][a] ----------------
__global__ void pos_kernel(const float* __restrict__ rh, const float* __restrict__ rw) {
    int idx = blockIdx.x * blockDim.x + threadIdx.x;
    if (idx >= 64 * NPIX) return;
    int d = idx >> 12, n = idx & 4095, a = n >> 6, bb = n & 63;
    g_pos[idx] = rh[d * 64 + bb] + rw[d * 64 + a];
}

// ---------------- flash attention ----------------
// S[i,j] = [q_i;pos_i] . [k_j;q_j]  (128-dim), softmax_j, O = P @ V^T.
// grid: (64 i-blocks, batch, branch). block 256, i-tile = 64 rows, j-tile = 64.
#define FLASH_SMEM ((8192 + 8192 + 64 * 68 + 64 * 65) * 4)
__global__ void __launch_bounds__(256) flash_kernel(
    const float* __restrict__ qg, const float* __restrict__ kg,
    const float* __restrict__ vg, float* __restrict__ outg)
{
    const int i0 = blockIdx.x * 64;
    const int b  = blockIdx.y;
    const int br = blockIdx.z;
    const long base = (long)(br * BATCH + b) * 64 * NPIX;
    const float* q = qg + base;
    const float* k = kg + base;
    const float* v = vg + base;
    float* outp = outg + (long)(b * 256 + br * 64) * NPIX;

    extern __shared__ float sm[];
    float* sQ = sm;                    // [128][64]
    float* sK = sm + 8192;             // [128][64]
    float* sV = sm + 16384;            // [64][68] : [j][d]
    float* sP = sm + 16384 + 64 * 68;  // [64][65] : [j][row]

    const int t = threadIdx.x, tx = t & 15, ty = t >> 4;

    // load Q' = [q ; pos] for this i-block
    for (int idx = t; idx < 8192; idx += 256) {
        int kk = idx >> 6, r = idx & 63;
        sQ[idx] = (kk < 64) ? q[kk * NPIX + i0 + r]
                            : g_pos[(kk - 64) * NPIX + i0 + r];
    }

    float m_[4], l_[4], O_[4][4];
#pragma unroll
    for (int r = 0; r < 4; r++) {
        m_[r] = -CUDART_INF_F; l_[r] = 0.f;
#pragma unroll
        for (int d = 0; d < 4; d++) O_[r][d] = 0.f;
    }

    for (int j0 = 0; j0 < NPIX; j0 += 64) {
        __syncthreads();   // protect sK/sV/sP from prior iteration; sQ visible on first iter
        for (int idx = t; idx < 8192; idx += 256) {
            int kk = idx >> 6, c = idx & 63;
            sK[idx] = (kk < 64) ? k[kk * NPIX + j0 + c]
                                : q[(kk - 64) * NPIX + j0 + c];
        }
        for (int idx = t; idx < 4096; idx += 256) {
            int dd = idx >> 6, jj = idx & 63;
            sV[jj * 68 + dd] = v[dd * NPIX + j0 + jj];
        }
        __syncthreads();

        // ---- S tile: 4x4 per thread over K=128 ----
        float s[4][4];
#pragma unroll
        for (int r = 0; r < 4; r++)
#pragma unroll
            for (int c = 0; c < 4; c++) s[r][c] = 0.f;

#pragma unroll 4
        for (int kk = 0; kk < 128; kk++) {
            float4 a  = *(const float4*)(sQ + kk * 64 + ty * 4);
            float4 kb = *(const float4*)(sK + kk * 64 + tx * 4);
            float av[4] = {a.x, a.y, a.z, a.w};
            float kv[4] = {kb.x, kb.y, kb.z, kb.w};
#pragma unroll
            for (int r = 0; r < 4; r++)
#pragma unroll
                for (int c = 0; c < 4; c++) s[r][c] += av[r] * kv[c];
        }

        // ---- online softmax (row groups = 16 lanes) ----
#pragma unroll
        for (int r = 0; r < 4; r++) {
            float mx = fmaxf(fmaxf(s[r][0], s[r][1]), fmaxf(s[r][2], s[r][3]));
            mx = fmaxf(mx, __shfl_xor_sync(0xffffffffu, mx, 1));
            mx = fmaxf(mx, __shfl_xor_sync(0xffffffffu, mx, 2));
            mx = fmaxf(mx, __shfl_xor_sync(0xffffffffu, mx, 4));
            mx = fmaxf(mx, __shfl_xor_sync(0xffffffffu, mx, 8));
            float mnew  = fmaxf(m_[r], mx);
            float alpha = __expf(m_[r] - mnew);
            float rsum = 0.f;
#pragma unroll
            for (int c = 0; c < 4; c++) {
                float p = __expf(s[r][c] - mnew);
                sP[(tx * 4 + c) * 65 + ty * 4 + r] = p;
                rsum += p;
            }
            rsum += __shfl_xor_sync(0xffffffffu, rsum, 1);
            rsum += __shfl_xor_sync(0xffffffffu, rsum, 2);
            rsum += __shfl_xor_sync(0xffffffffu, rsum, 4);
            rsum += __shfl_xor_sync(0xffffffffu, rsum, 8);
            l_[r] = l_[r] * alpha + rsum;
            m_[r] = mnew;
#pragma unroll
            for (int d = 0; d < 4; d++) O_[r][d] *= alpha;
        }
        __syncthreads();

        // ---- O += P @ V : per thread 4 rows x 4 d over 64 j ----
#pragma unroll 4
        for (int jj = 0; jj < 64; jj++) {
            float4 vv = *(const float4*)(sV + jj * 68 + tx * 4);
            float p0 = sP[jj * 65 + ty * 4 + 0];
            float p1 = sP[jj * 65 + ty * 4 + 1];
            float p2 = sP[jj * 65 + ty * 4 + 2];
            float p3 = sP[jj * 65 + ty * 4 + 3];
            O_[0][0] += p0 * vv.x; O_[0][1] += p0 * vv.y; O_[0][2] += p0 * vv.z; O_[0][3] += p0 * vv.w;
            O_[1][0] += p1 * vv.x; O_[1][1] += p1 * vv.y; O_[1][2] += p1 * vv.z; O_[1][3] += p1 * vv.w;
            O_[2][0] += p2 * vv.x; O_[2][1] += p2 * vv.y; O_[2][2] += p2 * vv.z; O_[2][3] += p2 * vv.w;
            O_[3][0] += p3 * vv.x; O_[3][1] += p3 * vv.y; O_[3][2] += p3 * vv.z; O_[3][3] += p3 * vv.w;
        }
    }

#pragma unroll
    for (int r = 0; r < 4; r++) {
        float inv = 1.f / l_[r];
        int pix = i0 + ty * 4 + r;
#pragma unroll
        for (int dd = 0; dd < 4; dd++)
            outp[(long)(tx * 4 + dd) * NPIX + pix] = O_[r][dd] * inv;
    }
}

// ---------------- host orchestration ----------------
extern "C" void kernel_launch(void* const* d_in, const int* in_sizes, int n_in,
                              void* d_out, int out_size) {
    const float* x      = (const float*)d_in[0];
    const float* dc_w1  = (const float*)d_in[1];
    // d_in[2] = dc_b1 : bias cancels in training-mode BN (constant per-channel shift)
    const float* dc_g1  = (const float*)d_in[3];
    const float* dc_be1 = (const float*)d_in[4];
    const float* dc_w2  = (const float*)d_in[5];
    // d_in[6] = dc_b2 : cancels
    const float* dc_g2  = (const float*)d_in[7];
    const float* dc_be2 = (const float*)d_in[8];
    const float* aw[4]  = {(const float*)d_in[9],  (const float*)d_in[12],
                           (const float*)d_in[15], (const float*)d_in[18]};
    const float* ag[4]  = {(const float*)d_in[10], (const float*)d_in[13],
                           (const float*)d_in[16], (const float*)d_in[19]};
    const float* ab[4]  = {(const float*)d_in[11], (const float*)d_in[14],
                           (const float*)d_in[17], (const float*)d_in[20]};
    const float* wq = (const float*)d_in[21]; const float* bq = (const float*)d_in[22];
    const float* wk = (const float*)d_in[23]; const float* bk = (const float*)d_in[24];
    const float* wv = (const float*)d_in[25]; const float* bv = (const float*)d_in[26];
    const float* rel_h = (const float*)d_in[27];
    const float* rel_w = (const float*)d_in[28];

    float *pool, *buf1, *buf2, *brb, *qb, *kb, *vb;
    cudaGetSymbolAddress((void**)&pool, g_pool);
    cudaGetSymbolAddress((void**)&buf1, g_buf1);
    cudaGetSymbolAddress((void**)&buf2, g_buf2);
    cudaGetSymbolAddress((void**)&brb,  g_br);
    cudaGetSymbolAddress((void**)&qb,   g_q);
    cudaGetSymbolAddress((void**)&kb,   g_k);
    cudaGetSymbolAddress((void**)&vb,   g_v);

    const int dils[4] = {1, 3, 6, 9};

    // mpconv
    maxpool_kernel<<<(BATCH * 128 * NPIX + 255) / 256, 256>>>(x, pool);
    conv3x3_kernel<<<dim3(64, 4, BATCH), 128>>>(pool, dc_w1, buf1, 128, 256, 1);
    bnstats_kernel<<<256, 256>>>(buf1, 256);
    bnapply_kernel<<<4096, 256>>>(buf1, dc_g1, dc_be1, 255, BATCH * 256 * NPIX);
    conv3x3_kernel<<<dim3(64, 4, BATCH), 128>>>(buf1, dc_w2, buf2, 256, 256, 1);
    bnstats_kernel<<<256, 256>>>(buf2, 256);
    bnapply_kernel<<<4096, 256>>>(buf2, dc_g2, dc_be2, 255, BATCH * 256 * NPIX);

    // ASPP branches (conv -> BN -> ReLU)
    for (int i = 0; i < 4; i++) {
        float* bro = brb + (long)i * BATCH * 64 * NPIX;
        if (dils[i] == 1) {
            conv1x1_kernel<<<dim3(64, 1, BATCH), 256>>>(
                buf2, aw[i], nullptr, bro, 256, (long)256 * NPIX, (long)64 * NPIX);
        } else {
            conv3x3_kernel<<<dim3(64, 1, BATCH), 128>>>(buf2, aw[i], bro, 256, 64, dils[i]);
        }
        bnstats_kernel<<<64, 256>>>(bro, 64);
        bnapply_kernel<<<4096, 256>>>(bro, ag[i], ab[i], 63, BATCH * 64 * NPIX);
    }

    // relative position table
    pos_kernel<<<(64 * NPIX + 255) / 256, 256>>>(rel_h, rel_w);

    // q, k, v projections for all 16 (branch, batch) images
    conv1x1_kernel<<<dim3(64, 1, 16), 256>>>(brb, wq, bq, qb, 64, (long)64 * NPIX, (long)64 * NPIX);
    conv1x1_kernel<<<dim3(64, 1, 16), 256>>>(brb, wk, bk, kb, 64, (long)64 * NPIX, (long)64 * NPIX);
    conv1x1_kernel<<<dim3(64, 1, 16), 256>>>(brb, wv, bv, vb, 64, (long)64 * NPIX, (long)64 * NPIX);

    // flash attention -> writes concat output directly
    cudaFuncSetAttribute((const void*)flash_kernel,
                         cudaFuncAttributeMaxDynamicSharedMemorySize, FLASH_SMEM);
    flash_kernel<<<dim3(64, BATCH, 4), 256, FLASH_SMEM>>>(qb, kb, vb, (float*)d_out);
}

// round 2
// speedup vs baseline: 1.4925x; 1.4925x over previous
#include <cuda_runtime.h>
#include <math_constants.h>
#include <stdint.h>

#define BATCH 4
#define NPIX 4096   // 64*64

// ---------------- scratch (device globals; no cudaMalloc allowed) ----------------
__device__ float g_pool[BATCH * 128 * NPIX];          // maxpool output
__device__ float g_buf1[BATCH * 256 * NPIX];          // conv1 out / h1
__device__ float g_buf2[BATCH * 256 * NPIX];          // conv2 out / h
__device__ float g_br  [4 * BATCH * 64 * NPIX];       // 4 ASPP branch outputs
__device__ float g_q   [4 * BATCH * 64 * NPIX];
__device__ float g_k   [4 * BATCH * 64 * NPIX];
__device__ float g_v   [4 * BATCH * 64 * NPIX];
__device__ float g_pos [64 * NPIX];
__device__ float g_mean[256];
__device__ float g_istd[256];

// ---------------- maxpool 2x2 on [4,128,128,128] -> [4,128,64,64] ----------------
__global__ void maxpool_kernel(const float* __restrict__ x, float* __restrict__ out) {
    int idx = blockIdx.x * blockDim.x + threadIdx.x;
    if (idx >= BATCH * 128 * NPIX) return;
    int p  = idx & (NPIX - 1);
    int bc = idx >> 12;                 // b*128 + c
    int y = p >> 6, xx = p & 63;
    const float* src = x + ((long)bc * 128 + 2 * y) * 128 + 2 * xx;
    out[idx] = fmaxf(fmaxf(src[0], src[1]), fmaxf(src[128], src[129]));
}

// ---------------- generic 3x3 dilated conv, pad=dil, no bias ----------------
__global__ void __launch_bounds__(128) conv3x3_kernel(
    const float* __restrict__ in, const float* __restrict__ w,
    float* __restrict__ out, int Cin, int Cout, int dil)
{
    const int y   = blockIdx.x;
    const int ocg = blockIdx.y;
    const int b   = blockIdx.z;
    in  += (long)b * Cin  * NPIX;
    out += (long)b * Cout * NPIX;

    const int t   = threadIdx.x;
    const int tpx = t & 15;       // pixel group (4 px each)
    const int tlo = t >> 4;       // oc lane (8 oc each)
    const int px0 = tpx * 4;

    __shared__ float sIn[8 * 3 * 64];   // [ic][ky][x]
    __shared__ float sW [72 * 68];      // [ic*9+tap][oc], 68-padded

    float acc[8][4];
#pragma unroll
    for (int o = 0; o < 8; o++)
#pragma unroll
        for (int p = 0; p < 4; p++) acc[o][p] = 0.f;

    for (int ic0 = 0; ic0 < Cin; ic0 += 8) {
        __syncthreads();
        for (int idx = t; idx < 1536; idx += 128) {
            int ic  = idx / 192;
            int rem = idx - ic * 192;
            int ky  = rem >> 6, xx = rem & 63;
            int ry  = y + (ky - 1) * dil;
            float v = 0.f;
            if (ry >= 0 && ry < 64) v = in[(ic0 + ic) * NPIX + ry * 64 + xx];
            sIn[idx] = v;
        }
        for (int idx = t; idx < 4608; idx += 128) {
            int oc = idx / 72;
            int kk = idx - oc * 72;   // ic*9 + tap
            sW[kk * 68 + oc] = w[((long)(ocg * 64 + oc) * Cin + ic0) * 9 + kk];
        }
        __syncthreads();

#pragma unroll
        for (int ic = 0; ic < 8; ic++) {
#pragma unroll
            for (int ky = 0; ky < 3; ky++) {
                const float* rowp = sIn + (ic * 3 + ky) * 64;
#pragma unroll
                for (int kx = 0; kx < 3; kx++) {
                    int xb = px0 + (kx - 1) * dil;
                    float iv[4];
                    iv[0] = (xb + 0 >= 0 && xb + 0 < 64) ? rowp[xb + 0] : 0.f;
                    iv[1] = (xb + 1 >= 0 && xb + 1 < 64) ? rowp[xb + 1] : 0.f;
                    iv[2] = (xb + 2 >= 0 && xb + 2 < 64) ? rowp[xb + 2] : 0.f;
                    iv[3] = (xb + 3 >= 0 && xb + 3 < 64) ? rowp[xb + 3] : 0.f;
                    const float* wp = sW + (ic * 9 + ky * 3 + kx) * 68 + tlo * 8;
                    float4 w0 = *(const float4*)wp;
                    float4 w1 = *(const float4*)(wp + 4);
                    float wv[8] = {w0.x, w0.y, w0.z, w0.w, w1.x, w1.y, w1.z, w1.w};
#pragma unroll
                    for (int o = 0; o < 8; o++)
#pragma unroll
                        for (int p = 0; p < 4; p++) acc[o][p] += wv[o] * iv[p];
                }
            }
        }
    }
#pragma unroll
    for (int o = 0; o < 8; o++) {
        int c = ocg * 64 + tlo * 8 + o;
        float* op = out + (long)c * NPIX + y * 64 + px0;
        op[0] = acc[o][0]; op[1] = acc[o][1]; op[2] = acc[o][2]; op[3] = acc[o][3];
    }
}

// ---------------- 1x1 conv (Cout=64), optional bias ----------------
__global__ void __launch_bounds__(256) conv1x1_kernel(
    const float* __restrict__ in, const float* __restrict__ w,
    const float* __restrict__ bias, float* __restrict__ out,
    int Cin, long inStride, long outStride)
{
    const int p0  = blockIdx.x * 64;
    const long img = blockIdx.z;
    in  += img * inStride;
    out += img * outStride;
    const int t = threadIdx.x, tx = t & 15, ty = t >> 4;

    __shared__ float sW [16 * 68];
    __shared__ float sIn[16 * 64];

    float acc[4][4];
#pragma unroll
    for (int r = 0; r < 4; r++)
#pragma unroll
        for (int c = 0; c < 4; c++) acc[r][c] = 0.f;

    for (int ic0 = 0; ic0 < Cin; ic0 += 16) {
        __syncthreads();
        for (int idx = t; idx < 1024; idx += 256) {
            int ic = idx & 15, oc = idx >> 4;
            sW[ic * 68 + oc] = w[(long)oc * Cin + ic0 + ic];
        }
        for (int idx = t; idx < 1024; idx += 256) {
            int ic = idx >> 6, px = idx & 63;
            sIn[idx] = in[(ic0 + ic) * NPIX + p0 + px];
        }
        __syncthreads();
#pragma unroll
        for (int ic = 0; ic < 16; ic++) {
            float4 a  = *(const float4*)(sW  + ic * 68 + ty * 4);
            float4 xv = *(const float4*)(sIn + ic * 64 + tx * 4);
            float av[4] = {a.x, a.y, a.z, a.w};
            float xa[4] = {xv.x, xv.y, xv.z, xv.w};
#pragma unroll
            for (int r = 0; r < 4; r++)
#pragma unroll
                for (int c = 0; c < 4; c++) acc[r][c] += av[r] * xa[c];
        }
    }
#pragma unroll
    for (int r = 0; r < 4; r++) {
        float bb = bias ? bias[ty * 4 + r] : 0.f;
        float* op = out + (long)(ty * 4 + r) * NPIX + p0 + tx * 4;
        op[0] = acc[r][0] + bb; op[1] = acc[r][1] + bb;
        op[2] = acc[r][2] + bb; op[3] = acc[r][3] + bb;
    }
}

// ---------------- BN batch statistics: one block per channel ----------------
__global__ void bnstats_kernel(const float* __restrict__ buf, int C) {
    const int c = blockIdx.x;
    float s = 0.f, ss = 0.f;
    for (int img = 0; img < BATCH; img++) {
        const float* p = buf + ((long)img * C + c) * NPIX;
        for (int i = threadIdx.x; i < NPIX; i += 256) {
            float v = p[i];
            s += v; ss += v * v;
        }
    }
    __shared__ float rs[8], rss[8];
#pragma unroll
    for (int off = 16; off; off >>= 1) {
        s  += __shfl_down_sync(0xffffffffu, s,  off);
        ss += __shfl_down_sync(0xffffffffu, ss, off);
    }
    int lane = threadIdx.x & 31, wp = threadIdx.x >> 5;
    if (!lane) { rs[wp] = s; rss[wp] = ss; }
    __syncthreads();
    if (threadIdx.x == 0) {
        s = 0.f; ss = 0.f;
        for (int i = 0; i < 8; i++) { s += rs[i]; ss += rss[i]; }
        const float M = (float)(BATCH * NPIX);
        float mu  = s / M;
        float var = ss / M - mu * mu;
        g_mean[c] = mu;
        g_istd[c] = rsqrtf(var + 1e-5f);
    }
}

// ---------------- BN apply + ReLU, in-place ----------------
__global__ void bnapply_kernel(float* __restrict__ buf, const float* __restrict__ g,
                               const float* __restrict__ be, int Cmask, int total) {
    for (int idx = blockIdx.x * blockDim.x + threadIdx.x; idx < total;
         idx += gridDim.x * blockDim.x) {
        int c = (idx >> 12) & Cmask;
        float v = buf[idx];
        float y = (v - g_mean[c]) * g_istd[c] * g[c] + be[c];
        buf[idx] = fmaxf(y, 0.f);
    }
}

// ---------------- pos[d][a*64+b] = rel_h[d][b] + rel_w[d][a] ----------------
__global__ void pos_kernel(const float* __restrict__ rh, const float* __restrict__ rw) {
    int idx = blockIdx.x * blockDim.x + threadIdx.x;
    if (idx >= 64 * NPIX) return;
    int d = idx >> 12, n = idx & 4095, a = n >> 6, bb = n & 63;
    g_pos[idx] = rh[d * 64 + bb] + rw[d * 64 + a];
}

// ================= tf32 tensor-core flash attention =================
// S[i,j] = [q_i;pos_i] . [k_j;q_j] (K=128), streaming softmax, O = P V^T.
// block = 256 thr (8 warps), i-tile = 128 (warp owns m16), j-tile = 64.
// mma.sync.m16n8k8 tf32. K'/V staged to smem PRE-converted to tf32 in an
// interleaved layout so each fragment pair (b0,b1)/(a0,a2) is one uint2 LDS.

__device__ __forceinline__ uint32_t f2tf32(float f) {
    uint32_t u;
    asm("cvt.rna.tf32.f32 %0, %1;" : "=r"(u) : "f"(f));
    return u;
}
__device__ __forceinline__ void mma8(float d[4], const uint32_t a[4],
                                     uint32_t b0, uint32_t b1) {
    asm volatile(
        "mma.sync.aligned.m16n8k8.row.col.f32.tf32.tf32.f32 "
        "{%0,%1,%2,%3},{%4,%5,%6,%7},{%8,%9},{%0,%1,%2,%3};"
        : "+f"(d[0]), "+f"(d[1]), "+f"(d[2]), "+f"(d[3])
        : "r"(a[0]), "r"(a[1]), "r"(a[2]), "r"(a[3]), "r"(b0), "r"(b1));
}

#define FLASH2_SMEM ((8192 + 4096 + 8192) * 4)   // sK + sV + sP = 80KB

__global__ void __launch_bounds__(256, 1) flash_mma_kernel(
    const float* __restrict__ qg, const float* __restrict__ kg,
    const float* __restrict__ vg, float* __restrict__ outg)
{
    extern __shared__ uint32_t smu[];
    uint32_t* sK = smu;            // [ks 16][j 64][8 interleaved k_lo]
    uint32_t* sV = smu + 8192;     // [ks 8][d 64][8 interleaved j_lo]
    uint32_t* sP = smu + 12288;    // [warp 8][ks 8][i 16][8 interleaved c_lo]

    const int i0 = blockIdx.x * 128;
    const int b  = blockIdx.y, br = blockIdx.z;
    const long base = (long)(br * BATCH + b) * 64 * NPIX;
    const float* q = qg + base;
    const float* k = kg + base;
    const float* v = vg + base;
    float* outp = outg + (long)(b * 256 + br * 64) * NPIX;

    const int t = threadIdx.x;
    const int lane = t & 31, w = t >> 5;
    const int g = lane >> 2, tq = lane & 3;

    // ---- Q' fragments (held in regs for entire kernel) ----
    uint32_t Qf[16][4];
    {
        int i_r = i0 + w * 16 + g;
#pragma unroll
        for (int ks = 0; ks < 16; ks++) {
            int kc = ks * 8 + tq;
            const float* s0 = (kc < 64)     ? (q + kc * NPIX)       : (g_pos + (kc - 64) * NPIX);
            const float* s1 = (kc + 4 < 64) ? (q + (kc + 4) * NPIX) : (g_pos + (kc - 60) * NPIX);
            Qf[ks][0] = f2tf32(s0[i_r]);
            Qf[ks][1] = f2tf32(s0[i_r + 8]);
            Qf[ks][2] = f2tf32(s1[i_r]);
            Qf[ks][3] = f2tf32(s1[i_r + 8]);
        }
    }

    float Oa[8][4];
#pragma unroll
    for (int nt = 0; nt < 8; nt++)
#pragma unroll
        for (int c = 0; c < 4; c++) Oa[nt][c] = 0.f;
    float m0 = -CUDART_INF_F, m1 = -CUDART_INF_F, l0 = 0.f, l1 = 0.f;

    // column interleave positions for P writes
    const int p00 = ((2 * tq) & 3) * 2 + (tq >> 1);            // col 2tq
    const int p01 = ((2 * tq + 1) & 3) * 2 + ((2 * tq + 1) >> 2); // col 2tq+1

    for (int j0 = 0; j0 < NPIX; j0 += 64) {
        __syncthreads();
        // ---- stage K' (128k x 64j), conflict-free lane decomposition ----
        for (int e = t; e < 8192; e += 256) {
            int klo = e & 7, joff = (e >> 3) & 3;
            int rest = e >> 5;
            int ks = rest & 15, jhi = rest >> 4;
            int j = jhi * 4 + joff;
            int kk = ks * 8 + klo;
            float val = (kk < 64) ? k[kk * NPIX + j0 + j]
                                  : q[(kk - 64) * NPIX + j0 + j];
            sK[ks * 512 + j * 8 + ((klo & 3) * 2 + (klo >> 2))] = f2tf32(val);
        }
        // ---- stage V (64j x 64d) ----
        for (int e = t; e < 4096; e += 256) {
            int jlo = e & 7, doff = (e >> 3) & 3;
            int rest = e >> 5;
            int ksv = rest & 7, dhi = rest >> 3;
            int dd = dhi * 4 + doff;
            int j = ksv * 8 + jlo;
            sV[ksv * 512 + dd * 8 + ((jlo & 3) * 2 + (jlo >> 2))] =
                f2tf32(v[dd * NPIX + j0 + j]);
        }
        __syncthreads();

        // ---- S = Q' K'  (16x64 per warp, K=128) ----
        float Sa[8][4];
#pragma unroll
        for (int nt = 0; nt < 8; nt++)
#pragma unroll
            for (int c = 0; c < 4; c++) Sa[nt][c] = 0.f;
#pragma unroll
        for (int ks = 0; ks < 16; ks++) {
#pragma unroll
            for (int nt = 0; nt < 8; nt++) {
                uint2 bb = *(const uint2*)&sK[ks * 512 + (nt * 8 + g) * 8 + 2 * tq];
                mma8(Sa[nt], Qf[ks], bb.x, bb.y);
            }
        }

        // ---- online softmax over this j-tile ----
        float mx0 = -CUDART_INF_F, mx1 = -CUDART_INF_F;
#pragma unroll
        for (int nt = 0; nt < 8; nt++) {
            mx0 = fmaxf(mx0, fmaxf(Sa[nt][0], Sa[nt][1]));
            mx1 = fmaxf(mx1, fmaxf(Sa[nt][2], Sa[nt][3]));
        }
        mx0 = fmaxf(mx0, __shfl_xor_sync(0xffffffffu, mx0, 1));
        mx0 = fmaxf(mx0, __shfl_xor_sync(0xffffffffu, mx0, 2));
        mx1 = fmaxf(mx1, __shfl_xor_sync(0xffffffffu, mx1, 1));
        mx1 = fmaxf(mx1, __shfl_xor_sync(0xffffffffu, mx1, 2));
        float mn0 = fmaxf(m0, mx0), mn1 = fmaxf(m1, mx1);
        float al0 = __expf(m0 - mn0), al1 = __expf(m1 - mn1);

        float su0 = 0.f, su1 = 0.f;
        const int pb = w * 1024 + g * 8;
#pragma unroll
        for (int nt = 0; nt < 8; nt++) {
            float e00 = __expf(Sa[nt][0] - mn0);
            float e01 = __expf(Sa[nt][1] - mn0);
            float e10 = __expf(Sa[nt][2] - mn1);
            float e11 = __expf(Sa[nt][3] - mn1);
            su0 += e00 + e01; su1 += e10 + e11;
            sP[pb + nt * 128 + p00]      = f2tf32(e00);
            sP[pb + nt * 128 + p01]      = f2tf32(e01);
            sP[pb + nt * 128 + 64 + p00] = f2tf32(e10);
            sP[pb + nt * 128 + 64 + p01] = f2tf32(e11);
        }
        su0 += __shfl_xor_sync(0xffffffffu, su0, 1);
        su0 += __shfl_xor_sync(0xffffffffu, su0, 2);
        su1 += __shfl_xor_sync(0xffffffffu, su1, 1);
        su1 += __shfl_xor_sync(0xffffffffu, su1, 2);
        l0 = l0 * al0 + su0; l1 = l1 * al1 + su1;
        m0 = mn0; m1 = mn1;
#pragma unroll
        for (int nt = 0; nt < 8; nt++) {
            Oa[nt][0] *= al0; Oa[nt][1] *= al0;
            Oa[nt][2] *= al1; Oa[nt][3] *= al1;
        }
        __syncwarp();

        // ---- O += P V  (16x64 per warp, K=64) ----
#pragma unroll
        for (int ks = 0; ks < 8; ks++) {
            const uint32_t* ap = &sP[w * 1024 + ks * 128 + g * 8 + 2 * tq];
            uint2 a02 = *(const uint2*)ap;
            uint2 a13 = *(const uint2*)(ap + 64);
            uint32_t a[4] = {a02.x, a13.x, a02.y, a13.y};
#pragma unroll
            for (int nt = 0; nt < 8; nt++) {
                uint2 bb = *(const uint2*)&sV[ks * 512 + (nt * 8 + g) * 8 + 2 * tq];
                mma8(Oa[nt], a, bb.x, bb.y);
            }
        }
    }

    // ---- epilogue ----
    float inv0 = 1.f / l0, inv1 = 1.f / l1;
    int pix = i0 + w * 16 + g;
#pragma unroll
    for (int nt = 0; nt < 8; nt++) {
        int d0 = nt * 8 + 2 * tq;
        outp[(long)d0 * NPIX + pix]           = Oa[nt][0] * inv0;
        outp[(long)(d0 + 1) * NPIX + pix]     = Oa[nt][1] * inv0;
        outp[(long)d0 * NPIX + pix + 8]       = Oa[nt][2] * inv1;
        outp[(long)(d0 + 1) * NPIX + pix + 8] = Oa[nt][3] * inv1;
    }
}

// ---------------- host orchestration ----------------
extern "C" void kernel_launch(void* const* d_in, const int* in_sizes, int n_in,
                              void* d_out, int out_size) {
    const float* x      = (const float*)d_in[0];
    const float* dc_w1  = (const float*)d_in[1];
    // d_in[2] = dc_b1 : bias cancels in training-mode BN
    const float* dc_g1  = (const float*)d_in[3];
    const float* dc_be1 = (const float*)d_in[4];
    const float* dc_w2  = (const float*)d_in[5];
    // d_in[6] = dc_b2 : cancels
    const float* dc_g2  = (const float*)d_in[7];
    const float* dc_be2 = (const float*)d_in[8];
    const float* aw[4]  = {(const float*)d_in[9],  (const float*)d_in[12],
                           (const float*)d_in[15], (const float*)d_in[18]};
    const float* ag[4]  = {(const float*)d_in[10], (const float*)d_in[13],
                           (const float*)d_in[16], (const float*)d_in[19]};
    const float* ab[4]  = {(const float*)d_in[11], (const float*)d_in[14],
                           (const float*)d_in[17], (const float*)d_in[20]};
    const float* wq = (const float*)d_in[21]; const float* bq = (const float*)d_in[22];
    const float* wk = (const float*)d_in[23]; const float* bk = (const float*)d_in[24];
    const float* wv = (const float*)d_in[25]; const float* bv = (const float*)d_in[26];
    const float* rel_h = (const float*)d_in[27];
    const float* rel_w = (const float*)d_in[28];

    float *pool, *buf1, *buf2, *brb, *qb, *kb, *vb;
    cudaGetSymbolAddress((void**)&pool, g_pool);
    cudaGetSymbolAddress((void**)&buf1, g_buf1);
    cudaGetSymbolAddress((void**)&buf2, g_buf2);
    cudaGetSymbolAddress((void**)&brb,  g_br);
    cudaGetSymbolAddress((void**)&qb,   g_q);
    cudaGetSymbolAddress((void**)&kb,   g_k);
    cudaGetSymbolAddress((void**)&vb,   g_v);

    const int dils[4] = {1, 3, 6, 9};

    // mpconv
    maxpool_kernel<<<(BATCH * 128 * NPIX + 255) / 256, 256>>>(x, pool);
    conv3x3_kernel<<<dim3(64, 4, BATCH), 128>>>(pool, dc_w1, buf1, 128, 256, 1);
    bnstats_kernel<<<256, 256>>>(buf1, 256);
    bnapply_kernel<<<4096, 256>>>(buf1, dc_g1, dc_be1, 255, BATCH * 256 * NPIX);
    conv3x3_kernel<<<dim3(64, 4, BATCH), 128>>>(buf1, dc_w2, buf2, 256, 256, 1);
    bnstats_kernel<<<256, 256>>>(buf2, 256);
    bnapply_kernel<<<4096, 256>>>(buf2, dc_g2, dc_be2, 255, BATCH * 256 * NPIX);

    // ASPP branches (conv -> BN -> ReLU)
    for (int i = 0; i < 4; i++) {
        float* bro = brb + (long)i * BATCH * 64 * NPIX;
        if (dils[i] == 1) {
            conv1x1_kernel<<<dim3(64, 1, BATCH), 256>>>(
                buf2, aw[i], nullptr, bro, 256, (long)256 * NPIX, (long)64 * NPIX);
        } else {
            conv3x3_kernel<<<dim3(64, 1, BATCH), 128>>>(buf2, aw[i], bro, 256, 64, dils[i]);
        }
        bnstats_kernel<<<64, 256>>>(bro, 64);
        bnapply_kernel<<<4096, 256>>>(bro, ag[i], ab[i], 63, BATCH * 64 * NPIX);
    }

    // relative position table
    pos_kernel<<<(64 * NPIX + 255) / 256, 256>>>(rel_h, rel_w);

    // q, k, v projections for all 16 (branch, batch) images
    conv1x1_kernel<<<dim3(64, 1, 16), 256>>>(brb, wq, bq, qb, 64, (long)64 * NPIX, (long)64 * NPIX);
    conv1x1_kernel<<<dim3(64, 1, 16), 256>>>(brb, wk, bk, kb, 64, (long)64 * NPIX, (long)64 * NPIX);
    conv1x1_kernel<<<dim3(64, 1, 16), 256>>>(brb, wv, bv, vb, 64, (long)64 * NPIX, (long)64 * NPIX);

    // tensor-core flash attention -> writes concat output directly
    cudaFuncSetAttribute((const void*)flash_mma_kernel,
                         cudaFuncAttributeMaxDynamicSharedMemorySize, FLASH2_SMEM);
    flash_mma_kernel<<<dim3(32, BATCH, 4), 256, FLASH2_SMEM>>>(qb, kb, vb, (float*)d_out);
}